// round 15
// baseline (speedup 1.0000x reference)
#include <cuda_runtime.h>
#include <cuda_fp16.h>
#include <math.h>
#include <stdint.h>

// Problem-fixed shapes: N=100000, C=256, H=128, K=64, E=1600000
#define NN   100000
#define EE   1600000
#define ETOT (EE + NN)
#define CDIM 256
#define HDIM 128
#define KOUT 64

// ---------------- device scratch (static, no allocation) ----------------
__device__ int    g_deg[NN];
__device__ int    g_incl[NN];
__device__ int    g_bsums[256];
__device__ int    g_rowptr[NN + 1];
__device__ int    g_pos[NN];
__device__ int    g_col[ETOT];
__device__ __half g_h1[NN * HDIM];
__device__ __half g_x1[NN * HDIM];
__device__ __half g_h2[NN * KOUT];
__device__ __half g_w1t[HDIM * CDIM];
__device__ __half g_w2t[KOUT * HDIM];
__device__ float  g_s1[NN], g_d1[NN], g_s2[NN], g_d2[NN];

// ---------------- combined weight transpose + fp16 convert ----------------
__global__ void wtrans_both_kernel(const float* __restrict__ W1, __half* __restrict__ WT1,
                                   const float* __restrict__ W2, __half* __restrict__ WT2) {
    int idx = blockIdx.x * blockDim.x + threadIdx.x;
    if (idx < HDIM * CDIM) {
        int n = idx / CDIM, k = idx % CDIM;
        WT1[idx] = __float2half(W1[(size_t)k * HDIM + n]);
    } else if (idx < HDIM * CDIM + KOUT * HDIM) {
        int j = idx - HDIM * CDIM;
        int n = j / HDIM, k = j % HDIM;
        WT2[j] = __float2half(W2[(size_t)k * KOUT + n]);
    }
}

// ---------------- CSR build (deg = edge count; +1 self-loop folded in finalize) ----------------
__global__ void hist_kernel(const int* __restrict__ dst, int* deg, int e) {
    int i = blockIdx.x * blockDim.x + threadIdx.x;
    if (i < e) atomicAdd(&deg[dst[i]], 1);
}
__global__ void scan_block_kernel(const int* __restrict__ deg, int* incl, int* bsums, int n) {
    __shared__ int sh[1024];
    int t = threadIdx.x;
    int gid = blockIdx.x * 1024 + t;
    sh[t] = (gid < n) ? deg[gid] : 0;
    __syncthreads();
    #pragma unroll
    for (int off = 1; off < 1024; off <<= 1) {
        int v = (t >= off) ? sh[t - off] : 0;
        __syncthreads();
        sh[t] += v;
        __syncthreads();
    }
    if (gid < n) incl[gid] = sh[t];
    if (t == 1023) bsums[blockIdx.x] = sh[t];
}
__global__ void scan_bsums_kernel(int* bsums, int nb) {
    __shared__ int sh[128];
    int t = threadIdx.x;
    sh[t] = (t < nb) ? bsums[t] : 0;
    __syncthreads();
    #pragma unroll
    for (int off = 1; off < 128; off <<= 1) {
        int v = (t >= off) ? sh[t - off] : 0;
        __syncthreads();
        sh[t] += v;
        __syncthreads();
    }
    if (t < nb) bsums[t] = (t == 0) ? 0 : sh[t - 1];
}
__global__ void finalize_rowptr_kernel(const int* __restrict__ incl, const int* __restrict__ bsums,
                                       const int* __restrict__ deg, int* rowptr, int* pos, int n) {
    int gid = blockIdx.x * blockDim.x + threadIdx.x;
    if (gid < n) {
        int v = incl[gid] + bsums[gid >> 10];
        rowptr[gid + 1] = v + gid + 1;
        pos[gid] = v + gid - deg[gid];
    }
    if (gid == 0) rowptr[0] = 0;
}
__global__ void scatter_kernel(const int* __restrict__ srcv, const int* __restrict__ dstv,
                               int* pos, int* colv, int e, int n) {
    int i = blockIdx.x * blockDim.x + threadIdx.x;
    if (i < e) {
        int p = atomicAdd(&pos[dstv[i]], 1);
        colv[p] = srcv[i];
    } else if (i < e + n) {
        int v = i - e;
        int p = atomicAdd(&pos[v], 1);
        colv[p] = v;
    }
}

// ---------------- asm helpers ----------------
__device__ __forceinline__ void cp_async16(void* smem_dst, const void* gmem_src, bool pred) {
    uint32_t saddr = (uint32_t)__cvta_generic_to_shared(smem_dst);
    int sz = pred ? 16 : 0;
    asm volatile("cp.async.cg.shared.global [%0], [%1], 16, %2;\n"
                 :: "r"(saddr), "l"(gmem_src), "r"(sz));
}
__device__ __forceinline__ void cp_commit() {
    asm volatile("cp.async.commit_group;\n");
}
template <int N>
__device__ __forceinline__ void cp_wait() {
    asm volatile("cp.async.wait_group %0;\n" :: "n"(N));
}
__device__ __forceinline__ uint32_t h2u(__half2 h) { return *reinterpret_cast<uint32_t*>(&h); }
__device__ __forceinline__ void ldsm_x4(uint32_t& r0, uint32_t& r1, uint32_t& r2, uint32_t& r3,
                                        uint32_t addr) {
    asm volatile("ldmatrix.sync.aligned.m8n8.x4.shared.b16 {%0,%1,%2,%3}, [%4];"
                 : "=r"(r0), "=r"(r1), "=r"(r2), "=r"(r3) : "r"(addr));
}
// 32B streaming read (v8.b32 is the minimum width ptxas accepts for L2::evict_first)
__device__ __forceinline__ void ldg_stream8(const float* p, float4& lo, float4& hi) {
    asm volatile("ld.global.nc.L2::evict_first.v8.f32 {%0,%1,%2,%3,%4,%5,%6,%7}, [%8];"
                 : "=f"(lo.x), "=f"(lo.y), "=f"(lo.z), "=f"(lo.w),
                   "=f"(hi.x), "=f"(hi.y), "=f"(hi.z), "=f"(hi.w) : "l"(p));
}

// ---------------- fp16 GEMM (m16n8k16): B fully preloaded, A 2-stage ----------------
template <int BN, int KD, bool CONVA>
__global__ __launch_bounds__(256) void mma_gemm_kernel(const void* __restrict__ Ap,
                                                       const __half* __restrict__ BT,
                                                       __half* __restrict__ Cmat,
                                                       const float* __restrict__ asrc,
                                                       const float* __restrict__ adst,
                                                       float* __restrict__ sv,
                                                       float* __restrict__ dv, int M) {
    constexpr int BM = 128, BK = 32;
    constexpr int WN = BN / 4;
    constexpr int MT = 4;
    constexpr int NT = WN / 8;
    constexpr int ST  = 40;
    constexpr int ST2 = KD + 8;
    constexpr int T = KD / BK;

    extern __shared__ __half sm[];
    __half* As = sm;                      // [2][BM][ST]
    __half* Bf = sm + 2 * BM * ST;        // [BN][ST2]

    int tid = threadIdx.x;
    int lane = tid & 31;
    int wid = tid >> 5;
    int wm = wid & 1;
    int wn = wid >> 1;
    int rowBase = blockIdx.x * BM;

    const float*  Af = (const float*)Ap;
    const __half* Ah = (const __half*)Ap;

    float acc[MT][NT][4];
    #pragma unroll
    for (int i = 0; i < MT; i++)
        #pragma unroll
        for (int j = 0; j < NT; j++)
            #pragma unroll
            for (int r = 0; r < 4; r++) acc[i][j][r] = 0.f;

    {
        constexpr int QR = KD / 8;
        constexpr int CH = BN * QR;
        constexpr int BIT = CH / 256;
        #pragma unroll
        for (int it = 0; it < BIT; it++) {
            int idx = tid + 256 * it;
            int n = idx / QR;
            int q = idx % QR;
            cp_async16(&Bf[n * ST2 + 8 * q], BT + (size_t)n * KD + 8 * q, true);
        }
        cp_commit();
    }

    float4 pa[2][2];
    auto ldgA = [&](int k0) {
        #pragma unroll
        for (int it = 0; it < 2; it++) {
            int idx = tid + 256 * it;
            int row = idx >> 2;
            int q = idx & 3;
            int gr = rowBase + row;
            if (gr < M) {
                ldg_stream8(Af + (size_t)gr * KD + k0 + 8 * q, pa[it][0], pa[it][1]);
            } else {
                pa[it][0] = make_float4(0.f, 0.f, 0.f, 0.f);
                pa[it][1] = make_float4(0.f, 0.f, 0.f, 0.f);
            }
        }
    };
    auto stsA = [&](int stage) {
        #pragma unroll
        for (int it = 0; it < 2; it++) {
            int idx = tid + 256 * it;
            int row = idx >> 2;
            int q = idx & 3;
            uint4 u;
            u.x = h2u(__floats2half2_rn(pa[it][0].x, pa[it][0].y));
            u.y = h2u(__floats2half2_rn(pa[it][0].z, pa[it][0].w));
            u.z = h2u(__floats2half2_rn(pa[it][1].x, pa[it][1].y));
            u.w = h2u(__floats2half2_rn(pa[it][1].z, pa[it][1].w));
            *reinterpret_cast<uint4*>(&As[(stage * BM + row) * ST + 8 * q]) = u;
        }
    };
    auto cpA = [&](int stage, int k0) {
        #pragma unroll
        for (int it = 0; it < 2; it++) {
            int idx = tid + 256 * it;
            int row = idx >> 2;
            int q = idx & 3;
            int gr = rowBase + row;
            cp_async16(&As[(stage * BM + row) * ST + 8 * q],
                       Ah + (size_t)gr * KD + k0 + 8 * q, gr < M);
        }
        cp_commit();
    };

    if (CONVA) ldgA(0);
    else       cpA(0, 0);

    int g = lane >> 3;
    int gl = lane & 7;

    for (int t = 0; t < T; t++) {
        int st = t & 1;
        if (CONVA) {
            stsA(st);
            if (t + 1 < T) ldgA((t + 1) * BK);
            if (t == 0) cp_wait<0>();
        } else {
            if (t + 1 < T) { cpA(st ^ 1, (t + 1) * BK); cp_wait<1>(); }
            else cp_wait<0>();
        }
        __syncthreads();

        #pragma unroll
        for (int kk = 0; kk < 2; kk++) {
            int kglob = t * BK + 16 * kk;
            uint32_t af[MT][4];
            #pragma unroll
            for (int mt = 0; mt < MT; mt++) {
                int row = wm * 64 + mt * 16 + ((g & 1) << 3) + gl;
                int colh = 16 * kk + ((g >> 1) << 3);
                uint32_t addr = (uint32_t)__cvta_generic_to_shared(
                    &As[(st * BM + row) * ST + colh]);
                ldsm_x4(af[mt][0], af[mt][1], af[mt][2], af[mt][3], addr);
            }
            uint32_t bf[NT][2];
            #pragma unroll
            for (int ntp = 0; ntp < NT / 2; ntp++) {
                int n = wn * WN + ntp * 16 + ((g >> 1) << 3) + gl;
                int colh = kglob + ((g & 1) << 3);
                uint32_t addr = (uint32_t)__cvta_generic_to_shared(&Bf[n * ST2 + colh]);
                ldsm_x4(bf[2 * ntp][0], bf[2 * ntp][1], bf[2 * ntp + 1][0], bf[2 * ntp + 1][1], addr);
            }
            #pragma unroll
            for (int mt = 0; mt < MT; mt++)
                #pragma unroll
                for (int nt = 0; nt < NT; nt++) {
                    asm volatile(
                        "mma.sync.aligned.m16n8k16.row.col.f32.f16.f16.f32 "
                        "{%0,%1,%2,%3}, {%4,%5,%6,%7}, {%8,%9}, {%0,%1,%2,%3};"
                        : "+f"(acc[mt][nt][0]), "+f"(acc[mt][nt][1]),
                          "+f"(acc[mt][nt][2]), "+f"(acc[mt][nt][3])
                        : "r"(af[mt][0]), "r"(af[mt][1]), "r"(af[mt][2]), "r"(af[mt][3]),
                          "r"(bf[nt][0]), "r"(bf[nt][1]));
                }
        }
        __syncthreads();
    }

    float* sred = reinterpret_cast<float*>(As);  // [2][BM]
    for (int t = tid; t < 2 * BM; t += 256) sred[t] = 0.f;
    __syncthreads();

    #pragma unroll
    for (int mt = 0; mt < MT; mt++) {
        int rl = wm * 64 + mt * 16 + (lane >> 2);
        int r0 = rowBase + rl;
        float s_lo = 0.f, d_lo = 0.f, s_hi = 0.f, d_hi = 0.f;
        #pragma unroll
        for (int nt = 0; nt < NT; nt++) {
            int col = wn * WN + nt * 8 + 2 * (lane & 3);
            float a0 = asrc[col], a1 = asrc[col + 1];
            float e0 = adst[col], e1 = adst[col + 1];
            s_lo += acc[mt][nt][0] * a0 + acc[mt][nt][1] * a1;
            d_lo += acc[mt][nt][0] * e0 + acc[mt][nt][1] * e1;
            s_hi += acc[mt][nt][2] * a0 + acc[mt][nt][3] * a1;
            d_hi += acc[mt][nt][2] * e0 + acc[mt][nt][3] * e1;
            if (r0 < M)
                *reinterpret_cast<__half2*>(Cmat + (size_t)r0 * BN + col) =
                    __floats2half2_rn(acc[mt][nt][0], acc[mt][nt][1]);
            if (r0 + 8 < M)
                *reinterpret_cast<__half2*>(Cmat + (size_t)(r0 + 8) * BN + col) =
                    __floats2half2_rn(acc[mt][nt][2], acc[mt][nt][3]);
        }
        #pragma unroll
        for (int o = 1; o <= 2; o <<= 1) {
            s_lo += __shfl_xor_sync(0xffffffffu, s_lo, o);
            d_lo += __shfl_xor_sync(0xffffffffu, d_lo, o);
            s_hi += __shfl_xor_sync(0xffffffffu, s_hi, o);
            d_hi += __shfl_xor_sync(0xffffffffu, d_hi, o);
        }
        if ((lane & 3) == 0) {
            atomicAdd(&sred[rl], s_lo);
            atomicAdd(&sred[BM + rl], d_lo);
            atomicAdd(&sred[rl + 8], s_hi);
            atomicAdd(&sred[BM + rl + 8], d_hi);
        }
    }
    __syncthreads();
    for (int t = tid; t < BM; t += 256) {
        int gr = rowBase + t;
        if (gr < M) { sv[gr] = sred[t]; dv[gr] = sred[BM + t]; }
    }
}

// ---------------- aggregation (fp16 gather; proven bcast4 form) ----------------
template <int F, int ACT, bool OUTH>
__global__ __launch_bounds__(512) void aggregate_kernel(
        const __half* __restrict__ h, const float* __restrict__ sv,
        const float* __restrict__ dv, const int* __restrict__ rowptr,
        const int* __restrict__ colidx, const float* __restrict__ bias,
        void* __restrict__ outp, int n) {
    constexpr int V = F / 32;
    int warp = (blockIdx.x * blockDim.x + threadIdx.x) >> 5;
    int lane = threadIdx.x & 31;
    if (warp >= n) return;
    int i = warp;
    int start = rowptr[i], end = rowptr[i + 1];
    int len = end - start;
    float di = dv[i];

    float a0 = 0.f, a1 = 0.f, a2 = 0.f, a3 = 0.f;
    float Z = 0.f;

    auto accum = [&](int s, float w) {
        if (V == 4) {
            uint2 u = *reinterpret_cast<const uint2*>(h + (size_t)s * F + 4 * lane);
            float2 f01 = __half22float2(*reinterpret_cast<__half2*>(&u.x));
            float2 f23 = __half22float2(*reinterpret_cast<__half2*>(&u.y));
            a0 += w * f01.x; a1 += w * f01.y; a2 += w * f23.x; a3 += w * f23.y;
        } else {
            __half2 u = *reinterpret_cast<const __half2*>(h + (size_t)s * F + 2 * lane);
            float2 f01 = __half22float2(u);
            a0 += w * f01.x; a1 += w * f01.y;
        }
    };
    auto bcast4 = [&](int sn, float w, int cnt) {
        int tt = 0;
        for (; tt + 4 <= cnt; tt += 4) {
            int s0 = __shfl_sync(0xffffffffu, sn, tt);
            int s1 = __shfl_sync(0xffffffffu, sn, tt + 1);
            int s2 = __shfl_sync(0xffffffffu, sn, tt + 2);
            int s3 = __shfl_sync(0xffffffffu, sn, tt + 3);
            float w0 = __shfl_sync(0xffffffffu, w, tt);
            float w1 = __shfl_sync(0xffffffffu, w, tt + 1);
            float w2 = __shfl_sync(0xffffffffu, w, tt + 2);
            float w3 = __shfl_sync(0xffffffffu, w, tt + 3);
            accum(s0, w0); accum(s1, w1); accum(s2, w2); accum(s3, w3);
        }
        for (; tt < cnt; tt++) {
            int sb = __shfl_sync(0xffffffffu, sn, tt);
            float wb = __shfl_sync(0xffffffffu, w, tt);
            accum(sb, wb);
        }
    };

    if (len <= 32) {
        int sn = 0;
        float x = -INFINITY;
        if (lane < len) {
            sn = colidx[start + lane];
            float xx = sv[sn] + di;
            x = (xx > 0.f) ? xx : 0.2f * xx;
        }
        float m = x;
        #pragma unroll
        for (int o = 16; o; o >>= 1) m = fmaxf(m, __shfl_xor_sync(0xffffffffu, m, o));
        float w = (lane < len) ? __expf(x - m) : 0.f;
        Z = w;
        #pragma unroll
        for (int o = 16; o; o >>= 1) Z += __shfl_xor_sync(0xffffffffu, Z, o);
        bcast4(sn, w, len);
    } else {
        float m = -INFINITY;
        for (int j = start + lane; j < end; j += 32) {
            float x = sv[colidx[j]] + di;
            x = (x > 0.f) ? x : 0.2f * x;
            m = fmaxf(m, x);
        }
        #pragma unroll
        for (int o = 16; o; o >>= 1) m = fmaxf(m, __shfl_xor_sync(0xffffffffu, m, o));

        for (int j0 = start; j0 < end; j0 += 32) {
            int j = j0 + lane;
            int sn = 0;
            float w = 0.f;
            if (j < end) {
                sn = colidx[j];
                float x = sv[sn] + di;
                x = (x > 0.f) ? x : 0.2f * x;
                w = __expf(x - m);
                Z += w;
            }
            bcast4(sn, w, min(32, end - j0));
        }
        #pragma unroll
        for (int o = 16; o; o >>= 1) Z += __shfl_xor_sync(0xffffffffu, Z, o);
    }

    float invZ = 1.f / (Z + 1e-16f);
    float r0, r1, r2 = 0.f, r3 = 0.f;
    if (V == 4) {
        float4 bb = *reinterpret_cast<const float4*>(bias + 4 * lane);
        r0 = a0 * invZ + bb.x; r1 = a1 * invZ + bb.y;
        r2 = a2 * invZ + bb.z; r3 = a3 * invZ + bb.w;
    } else {
        float2 bb = *reinterpret_cast<const float2*>(bias + 2 * lane);
        r0 = a0 * invZ + bb.x; r1 = a1 * invZ + bb.y;
    }
    if (ACT == 0) {
        r0 = fmaxf(r0, 0.f); r1 = fmaxf(r1, 0.f);
        r2 = fmaxf(r2, 0.f); r3 = fmaxf(r3, 0.f);
    } else {
        r0 = 1.f / (1.f + __expf(-r0)); r1 = 1.f / (1.f + __expf(-r1));
        r2 = 1.f / (1.f + __expf(-r2)); r3 = 1.f / (1.f + __expf(-r3));
    }

    if (OUTH) {
        __half* out = (__half*)outp;
        if (V == 4) {
            uint2 u;
            u.x = h2u(__floats2half2_rn(r0, r1));
            u.y = h2u(__floats2half2_rn(r2, r3));
            *reinterpret_cast<uint2*>(out + (size_t)i * F + 4 * lane) = u;
        } else {
            *reinterpret_cast<__half2*>(out + (size_t)i * F + 2 * lane) =
                __floats2half2_rn(r0, r1);
        }
    } else {
        float* out = (float*)outp;
        if (V == 4)
            *reinterpret_cast<float4*>(out + (size_t)i * F + 4 * lane) =
                make_float4(r0, r1, r2, r3);
        else
            *reinterpret_cast<float2*>(out + (size_t)i * F + 2 * lane) =
                make_float2(r0, r1);
    }
}

// ---------------- host launch ----------------
static inline int cdiv(int a, int b) { return (a + b - 1) / b; }

extern "C" void kernel_launch(void* const* d_in, const int* in_sizes, int n_in,
                              void* d_out, int out_size) {
    const int*   ei    = (const int*)d_in[0];
    const float* embed = (const float*)d_in[1];
    const float* W1    = (const float*)d_in[2];
    const float* as1   = (const float*)d_in[3];
    const float* ad1   = (const float*)d_in[4];
    const float* b1    = (const float*)d_in[5];
    const float* W2    = (const float*)d_in[6];
    const float* as2   = (const float*)d_in[7];
    const float* ad2   = (const float*)d_in[8];
    const float* b2    = (const float*)d_in[9];

    int E = in_sizes[0] / 2;
    int N = in_sizes[1] / CDIM;
    const int* srcv = ei;
    const int* dstv = ei + E;

    void* p;
    cudaGetSymbolAddress(&p, g_deg);    int* deg    = (int*)p;
    cudaGetSymbolAddress(&p, g_incl);   int* incl   = (int*)p;
    cudaGetSymbolAddress(&p, g_bsums);  int* bsums  = (int*)p;
    cudaGetSymbolAddress(&p, g_rowptr); int* rowptr = (int*)p;
    cudaGetSymbolAddress(&p, g_pos);    int* pos    = (int*)p;
    cudaGetSymbolAddress(&p, g_col);    int* col    = (int*)p;
    cudaGetSymbolAddress(&p, g_h1);     __half* h1  = (__half*)p;
    cudaGetSymbolAddress(&p, g_x1);     __half* x1  = (__half*)p;
    cudaGetSymbolAddress(&p, g_h2);     __half* h2  = (__half*)p;
    cudaGetSymbolAddress(&p, g_w1t);    __half* w1t = (__half*)p;
    cudaGetSymbolAddress(&p, g_w2t);    __half* w2t = (__half*)p;
    cudaGetSymbolAddress(&p, g_s1);     float* s1   = (float*)p;
    cudaGetSymbolAddress(&p, g_d1);     float* d1   = (float*)p;
    cudaGetSymbolAddress(&p, g_s2);     float* s2   = (float*)p;
    cudaGetSymbolAddress(&p, g_d2);     float* d2   = (float*)p;
    float* out = (float*)d_out;

    int nb = cdiv(N, 1024);

    constexpr int SMEM1 = (2 * 128 * 40 + 128 * (CDIM + 8)) * 2;  // 88064
    constexpr int SMEM2 = (2 * 128 * 40 + 64 * (HDIM + 8)) * 2;   // 37888

    static cudaStream_t s_side = nullptr;
    static cudaEvent_t ev_fork = nullptr, ev_join = nullptr;
    if (!s_side) {
        cudaStreamCreateWithFlags(&s_side, cudaStreamNonBlocking);
        cudaEventCreateWithFlags(&ev_fork, cudaEventDisableTiming);
        cudaEventCreateWithFlags(&ev_join, cudaEventDisableTiming);
        cudaFuncSetAttribute(mma_gemm_kernel<HDIM, CDIM, true>,
                             cudaFuncAttributeMaxDynamicSharedMemorySize, SMEM1);
        cudaFuncSetAttribute(mma_gemm_kernel<KOUT, HDIM, false>,
                             cudaFuncAttributeMaxDynamicSharedMemorySize, SMEM2);
    }

    // fork: CSR build on side stream (depends only on edge_index)
    cudaEventRecord(ev_fork, 0);
    cudaStreamWaitEvent(s_side, ev_fork, 0);
    cudaMemsetAsync(deg, 0, N * sizeof(int), s_side);
    hist_kernel<<<cdiv(E, 256), 256, 0, s_side>>>(dstv, deg, E);
    scan_block_kernel<<<nb, 1024, 0, s_side>>>(deg, incl, bsums, N);
    scan_bsums_kernel<<<1, 128, 0, s_side>>>(bsums, nb);
    finalize_rowptr_kernel<<<cdiv(N + 1, 256), 256, 0, s_side>>>(incl, bsums, deg, rowptr, pos, N);
    scatter_kernel<<<cdiv(E + N, 256), 256, 0, s_side>>>(srcv, dstv, pos, col, E, N);
    cudaEventRecord(ev_join, s_side);

    // main (overlapped with CSR): weights + GEMM1 (embed loads use L2::evict_first)
    wtrans_both_kernel<<<cdiv(HDIM * CDIM + KOUT * HDIM, 256), 256>>>(W1, w1t, W2, w2t);
    mma_gemm_kernel<HDIM, CDIM, true><<<cdiv(N, 128), 256, SMEM1>>>(
        embed, w1t, h1, as1, ad1, s1, d1, N);

    // join: aggregation needs CSR + h1 (h1 L2-resident thanks to evict-first embed stream)
    cudaStreamWaitEvent(0, ev_join, 0);
    aggregate_kernel<HDIM, 0, true><<<cdiv(N, 16), 512>>>(h1, s1, d1, rowptr, col, b1, x1, N);

    mma_gemm_kernel<KOUT, HDIM, false><<<cdiv(N, 128), 256, SMEM2>>>(
        x1, w2t, h2, as2, ad2, s2, d2, N);
    aggregate_kernel<KOUT, 1, false><<<cdiv(N, 16), 512>>>(h2, s2, d2, rowptr, col, b2, out, N);
}

// round 16
// speedup vs baseline: 1.0322x; 1.0322x over previous
#include <cuda_runtime.h>
#include <cuda_fp16.h>
#include <math.h>
#include <stdint.h>

// Problem-fixed shapes: N=100000, C=256, H=128, K=64, E=1600000
#define NN   100000
#define EE   1600000
#define ETOT (EE + NN)
#define CDIM 256
#define HDIM 128
#define KOUT 64

// ---------------- device scratch (static, no allocation) ----------------
__device__ int    g_deg[NN];
__device__ int    g_incl[NN];
__device__ int    g_bsums[256];
__device__ int    g_rowptr[NN + 1];
__device__ int    g_pos[NN];
__device__ int    g_col[ETOT];
__device__ __half g_h1[NN * HDIM];
__device__ __half g_x1[NN * HDIM];
__device__ __half g_h2[NN * KOUT];
__device__ __half g_w1t[HDIM * CDIM];
__device__ __half g_w2t[KOUT * HDIM];
__device__ float  g_s1[NN], g_d1[NN], g_s2[NN], g_d2[NN];

// ---------------- combined weight transpose + fp16 convert ----------------
__global__ void wtrans_both_kernel(const float* __restrict__ W1, __half* __restrict__ WT1,
                                   const float* __restrict__ W2, __half* __restrict__ WT2) {
    int idx = blockIdx.x * blockDim.x + threadIdx.x;
    if (idx < HDIM * CDIM) {
        int n = idx / CDIM, k = idx % CDIM;
        WT1[idx] = __float2half(W1[(size_t)k * HDIM + n]);
    } else if (idx < HDIM * CDIM + KOUT * HDIM) {
        int j = idx - HDIM * CDIM;
        int n = j / HDIM, k = j % HDIM;
        WT2[j] = __float2half(W2[(size_t)k * KOUT + n]);
    }
}

// ---------------- CSR build (deg = edge count; +1 self-loop folded in finalize) ----------------
__global__ void hist_kernel(const int* __restrict__ dst, int* deg, int e) {
    int i = blockIdx.x * blockDim.x + threadIdx.x;
    if (i < e) atomicAdd(&deg[dst[i]], 1);
}
__global__ void scan_block_kernel(const int* __restrict__ deg, int* incl, int* bsums, int n) {
    __shared__ int sh[1024];
    int t = threadIdx.x;
    int gid = blockIdx.x * 1024 + t;
    sh[t] = (gid < n) ? deg[gid] : 0;
    __syncthreads();
    #pragma unroll
    for (int off = 1; off < 1024; off <<= 1) {
        int v = (t >= off) ? sh[t - off] : 0;
        __syncthreads();
        sh[t] += v;
        __syncthreads();
    }
    if (gid < n) incl[gid] = sh[t];
    if (t == 1023) bsums[blockIdx.x] = sh[t];
}
__global__ void scan_bsums_kernel(int* bsums, int nb) {
    __shared__ int sh[128];
    int t = threadIdx.x;
    sh[t] = (t < nb) ? bsums[t] : 0;
    __syncthreads();
    #pragma unroll
    for (int off = 1; off < 128; off <<= 1) {
        int v = (t >= off) ? sh[t - off] : 0;
        __syncthreads();
        sh[t] += v;
        __syncthreads();
    }
    if (t < nb) bsums[t] = (t == 0) ? 0 : sh[t - 1];
}
__global__ void finalize_rowptr_kernel(const int* __restrict__ incl, const int* __restrict__ bsums,
                                       const int* __restrict__ deg, int* rowptr, int* pos, int n) {
    int gid = blockIdx.x * blockDim.x + threadIdx.x;
    if (gid < n) {
        int v = incl[gid] + bsums[gid >> 10];
        rowptr[gid + 1] = v + gid + 1;
        pos[gid] = v + gid - deg[gid];
    }
    if (gid == 0) rowptr[0] = 0;
}
__global__ void scatter_kernel(const int* __restrict__ srcv, const int* __restrict__ dstv,
                               int* pos, int* colv, int e, int n) {
    int i = blockIdx.x * blockDim.x + threadIdx.x;
    if (i < e) {
        int p = atomicAdd(&pos[dstv[i]], 1);
        colv[p] = srcv[i];
    } else if (i < e + n) {
        int v = i - e;
        int p = atomicAdd(&pos[v], 1);
        colv[p] = v;
    }
}

// ---------------- asm helpers ----------------
__device__ __forceinline__ void cp_async16(void* smem_dst, const void* gmem_src, bool pred) {
    uint32_t saddr = (uint32_t)__cvta_generic_to_shared(smem_dst);
    int sz = pred ? 16 : 0;
    asm volatile("cp.async.cg.shared.global [%0], [%1], 16, %2;\n"
                 :: "r"(saddr), "l"(gmem_src), "r"(sz));
}
__device__ __forceinline__ void cp_commit() {
    asm volatile("cp.async.commit_group;\n");
}
template <int N>
__device__ __forceinline__ void cp_wait() {
    asm volatile("cp.async.wait_group %0;\n" :: "n"(N));
}
__device__ __forceinline__ uint32_t h2u(__half2 h) { return *reinterpret_cast<uint32_t*>(&h); }
__device__ __forceinline__ void ldsm_x4(uint32_t& r0, uint32_t& r1, uint32_t& r2, uint32_t& r3,
                                        uint32_t addr) {
    asm volatile("ldmatrix.sync.aligned.m8n8.x4.shared.b16 {%0,%1,%2,%3}, [%4];"
                 : "=r"(r0), "=r"(r1), "=r"(r2), "=r"(r3) : "r"(addr));
}
// 32B streaming read (v8.b32 is the minimum width ptxas accepts for L2::evict_first)
__device__ __forceinline__ void ldg_stream8(const float* p, float4& lo, float4& hi) {
    asm volatile("ld.global.nc.L2::evict_first.v8.f32 {%0,%1,%2,%3,%4,%5,%6,%7}, [%8];"
                 : "=f"(lo.x), "=f"(lo.y), "=f"(lo.z), "=f"(lo.w),
                   "=f"(hi.x), "=f"(hi.y), "=f"(hi.z), "=f"(hi.w) : "l"(p));
}

// ---------------- fp16 GEMM (m16n8k16): B fully preloaded, A 2-stage ----------------
template <int BN, int KD, bool CONVA>
__global__ __launch_bounds__(256) void mma_gemm_kernel(const void* __restrict__ Ap,
                                                       const __half* __restrict__ BT,
                                                       __half* __restrict__ Cmat,
                                                       const float* __restrict__ asrc,
                                                       const float* __restrict__ adst,
                                                       float* __restrict__ sv,
                                                       float* __restrict__ dv, int M) {
    constexpr int BM = 128, BK = 32;
    constexpr int WN = BN / 4;
    constexpr int MT = 4;
    constexpr int NT = WN / 8;
    constexpr int ST  = 40;
    constexpr int ST2 = KD + 8;
    constexpr int T = KD / BK;

    extern __shared__ __half sm[];
    __half* As = sm;                      // [2][BM][ST]
    __half* Bf = sm + 2 * BM * ST;        // [BN][ST2]

    int tid = threadIdx.x;
    int lane = tid & 31;
    int wid = tid >> 5;
    int wm = wid & 1;
    int wn = wid >> 1;
    int rowBase = blockIdx.x * BM;

    const float*  Af = (const float*)Ap;
    const __half* Ah = (const __half*)Ap;

    float acc[MT][NT][4];
    #pragma unroll
    for (int i = 0; i < MT; i++)
        #pragma unroll
        for (int j = 0; j < NT; j++)
            #pragma unroll
            for (int r = 0; r < 4; r++) acc[i][j][r] = 0.f;

    {
        constexpr int QR = KD / 8;
        constexpr int CH = BN * QR;
        constexpr int BIT = CH / 256;
        #pragma unroll
        for (int it = 0; it < BIT; it++) {
            int idx = tid + 256 * it;
            int n = idx / QR;
            int q = idx % QR;
            cp_async16(&Bf[n * ST2 + 8 * q], BT + (size_t)n * KD + 8 * q, true);
        }
        cp_commit();
    }

    float4 pa[2][2];
    auto ldgA = [&](int k0) {
        #pragma unroll
        for (int it = 0; it < 2; it++) {
            int idx = tid + 256 * it;
            int row = idx >> 2;
            int q = idx & 3;
            int gr = rowBase + row;
            if (gr < M) {
                ldg_stream8(Af + (size_t)gr * KD + k0 + 8 * q, pa[it][0], pa[it][1]);
            } else {
                pa[it][0] = make_float4(0.f, 0.f, 0.f, 0.f);
                pa[it][1] = make_float4(0.f, 0.f, 0.f, 0.f);
            }
        }
    };
    auto stsA = [&](int stage) {
        #pragma unroll
        for (int it = 0; it < 2; it++) {
            int idx = tid + 256 * it;
            int row = idx >> 2;
            int q = idx & 3;
            uint4 u;
            u.x = h2u(__floats2half2_rn(pa[it][0].x, pa[it][0].y));
            u.y = h2u(__floats2half2_rn(pa[it][0].z, pa[it][0].w));
            u.z = h2u(__floats2half2_rn(pa[it][1].x, pa[it][1].y));
            u.w = h2u(__floats2half2_rn(pa[it][1].z, pa[it][1].w));
            *reinterpret_cast<uint4*>(&As[(stage * BM + row) * ST + 8 * q]) = u;
        }
    };
    auto cpA = [&](int stage, int k0) {
        #pragma unroll
        for (int it = 0; it < 2; it++) {
            int idx = tid + 256 * it;
            int row = idx >> 2;
            int q = idx & 3;
            int gr = rowBase + row;
            cp_async16(&As[(stage * BM + row) * ST + 8 * q],
                       Ah + (size_t)gr * KD + k0 + 8 * q, gr < M);
        }
        cp_commit();
    };

    if (CONVA) ldgA(0);
    else       cpA(0, 0);

    int g = lane >> 3;
    int gl = lane & 7;

    for (int t = 0; t < T; t++) {
        int st = t & 1;
        if (CONVA) {
            stsA(st);
            if (t + 1 < T) ldgA((t + 1) * BK);
            if (t == 0) cp_wait<0>();
        } else {
            if (t + 1 < T) { cpA(st ^ 1, (t + 1) * BK); cp_wait<1>(); }
            else cp_wait<0>();
        }
        __syncthreads();

        #pragma unroll
        for (int kk = 0; kk < 2; kk++) {
            int kglob = t * BK + 16 * kk;
            uint32_t af[MT][4];
            #pragma unroll
            for (int mt = 0; mt < MT; mt++) {
                int row = wm * 64 + mt * 16 + ((g & 1) << 3) + gl;
                int colh = 16 * kk + ((g >> 1) << 3);
                uint32_t addr = (uint32_t)__cvta_generic_to_shared(
                    &As[(st * BM + row) * ST + colh]);
                ldsm_x4(af[mt][0], af[mt][1], af[mt][2], af[mt][3], addr);
            }
            uint32_t bf[NT][2];
            #pragma unroll
            for (int ntp = 0; ntp < NT / 2; ntp++) {
                int n = wn * WN + ntp * 16 + ((g >> 1) << 3) + gl;
                int colh = kglob + ((g & 1) << 3);
                uint32_t addr = (uint32_t)__cvta_generic_to_shared(&Bf[n * ST2 + colh]);
                ldsm_x4(bf[2 * ntp][0], bf[2 * ntp][1], bf[2 * ntp + 1][0], bf[2 * ntp + 1][1], addr);
            }
            #pragma unroll
            for (int mt = 0; mt < MT; mt++)
                #pragma unroll
                for (int nt = 0; nt < NT; nt++) {
                    asm volatile(
                        "mma.sync.aligned.m16n8k16.row.col.f32.f16.f16.f32 "
                        "{%0,%1,%2,%3}, {%4,%5,%6,%7}, {%8,%9}, {%0,%1,%2,%3};"
                        : "+f"(acc[mt][nt][0]), "+f"(acc[mt][nt][1]),
                          "+f"(acc[mt][nt][2]), "+f"(acc[mt][nt][3])
                        : "r"(af[mt][0]), "r"(af[mt][1]), "r"(af[mt][2]), "r"(af[mt][3]),
                          "r"(bf[nt][0]), "r"(bf[nt][1]));
                }
        }
        __syncthreads();
    }

    float* sred = reinterpret_cast<float*>(As);  // [2][BM]
    for (int t = tid; t < 2 * BM; t += 256) sred[t] = 0.f;
    __syncthreads();

    #pragma unroll
    for (int mt = 0; mt < MT; mt++) {
        int rl = wm * 64 + mt * 16 + (lane >> 2);
        int r0 = rowBase + rl;
        float s_lo = 0.f, d_lo = 0.f, s_hi = 0.f, d_hi = 0.f;
        #pragma unroll
        for (int nt = 0; nt < NT; nt++) {
            int col = wn * WN + nt * 8 + 2 * (lane & 3);
            float a0 = asrc[col], a1 = asrc[col + 1];
            float e0 = adst[col], e1 = adst[col + 1];
            s_lo += acc[mt][nt][0] * a0 + acc[mt][nt][1] * a1;
            d_lo += acc[mt][nt][0] * e0 + acc[mt][nt][1] * e1;
            s_hi += acc[mt][nt][2] * a0 + acc[mt][nt][3] * a1;
            d_hi += acc[mt][nt][2] * e0 + acc[mt][nt][3] * e1;
            if (r0 < M)
                *reinterpret_cast<__half2*>(Cmat + (size_t)r0 * BN + col) =
                    __floats2half2_rn(acc[mt][nt][0], acc[mt][nt][1]);
            if (r0 + 8 < M)
                *reinterpret_cast<__half2*>(Cmat + (size_t)(r0 + 8) * BN + col) =
                    __floats2half2_rn(acc[mt][nt][2], acc[mt][nt][3]);
        }
        #pragma unroll
        for (int o = 1; o <= 2; o <<= 1) {
            s_lo += __shfl_xor_sync(0xffffffffu, s_lo, o);
            d_lo += __shfl_xor_sync(0xffffffffu, d_lo, o);
            s_hi += __shfl_xor_sync(0xffffffffu, s_hi, o);
            d_hi += __shfl_xor_sync(0xffffffffu, d_hi, o);
        }
        if ((lane & 3) == 0) {
            atomicAdd(&sred[rl], s_lo);
            atomicAdd(&sred[BM + rl], d_lo);
            atomicAdd(&sred[rl + 8], s_hi);
            atomicAdd(&sred[BM + rl + 8], d_hi);
        }
    }
    __syncthreads();
    for (int t = tid; t < BM; t += 256) {
        int gr = rowBase + t;
        if (gr < M) { sv[gr] = sred[t]; dv[gr] = sred[BM + t]; }
    }
}

// ---------------- aggregation (fp16 gather; proven bcast4 form) ----------------
template <int F, int ACT, bool OUTH>
__global__ __launch_bounds__(256) void aggregate_kernel(
        const __half* __restrict__ h, const float* __restrict__ sv,
        const float* __restrict__ dv, const int* __restrict__ rowptr,
        const int* __restrict__ colidx, const float* __restrict__ bias,
        void* __restrict__ outp, int n) {
    constexpr int V = F / 32;
    int warp = (blockIdx.x * blockDim.x + threadIdx.x) >> 5;
    int lane = threadIdx.x & 31;
    if (warp >= n) return;
    int i = warp;
    int start = rowptr[i], end = rowptr[i + 1];
    int len = end - start;
    float di = dv[i];

    float a0 = 0.f, a1 = 0.f, a2 = 0.f, a3 = 0.f;
    float Z = 0.f;

    auto accum = [&](int s, float w) {
        if (V == 4) {
            uint2 u = *reinterpret_cast<const uint2*>(h + (size_t)s * F + 4 * lane);
            float2 f01 = __half22float2(*reinterpret_cast<__half2*>(&u.x));
            float2 f23 = __half22float2(*reinterpret_cast<__half2*>(&u.y));
            a0 += w * f01.x; a1 += w * f01.y; a2 += w * f23.x; a3 += w * f23.y;
        } else {
            __half2 u = *reinterpret_cast<const __half2*>(h + (size_t)s * F + 2 * lane);
            float2 f01 = __half22float2(u);
            a0 += w * f01.x; a1 += w * f01.y;
        }
    };
    auto bcast4 = [&](int sn, float w, int cnt) {
        int tt = 0;
        for (; tt + 4 <= cnt; tt += 4) {
            int s0 = __shfl_sync(0xffffffffu, sn, tt);
            int s1 = __shfl_sync(0xffffffffu, sn, tt + 1);
            int s2 = __shfl_sync(0xffffffffu, sn, tt + 2);
            int s3 = __shfl_sync(0xffffffffu, sn, tt + 3);
            float w0 = __shfl_sync(0xffffffffu, w, tt);
            float w1 = __shfl_sync(0xffffffffu, w, tt + 1);
            float w2 = __shfl_sync(0xffffffffu, w, tt + 2);
            float w3 = __shfl_sync(0xffffffffu, w, tt + 3);
            accum(s0, w0); accum(s1, w1); accum(s2, w2); accum(s3, w3);
        }
        for (; tt < cnt; tt++) {
            int sb = __shfl_sync(0xffffffffu, sn, tt);
            float wb = __shfl_sync(0xffffffffu, w, tt);
            accum(sb, wb);
        }
    };

    if (len <= 32) {
        int sn = 0;
        float x = -INFINITY;
        if (lane < len) {
            sn = colidx[start + lane];
            float xx = sv[sn] + di;
            x = (xx > 0.f) ? xx : 0.2f * xx;
        }
        float m = x;
        #pragma unroll
        for (int o = 16; o; o >>= 1) m = fmaxf(m, __shfl_xor_sync(0xffffffffu, m, o));
        float w = (lane < len) ? __expf(x - m) : 0.f;
        Z = w;
        #pragma unroll
        for (int o = 16; o; o >>= 1) Z += __shfl_xor_sync(0xffffffffu, Z, o);
        bcast4(sn, w, len);
    } else {
        float m = -INFINITY;
        for (int j = start + lane; j < end; j += 32) {
            float x = sv[colidx[j]] + di;
            x = (x > 0.f) ? x : 0.2f * x;
            m = fmaxf(m, x);
        }
        #pragma unroll
        for (int o = 16; o; o >>= 1) m = fmaxf(m, __shfl_xor_sync(0xffffffffu, m, o));

        for (int j0 = start; j0 < end; j0 += 32) {
            int j = j0 + lane;
            int sn = 0;
            float w = 0.f;
            if (j < end) {
                sn = colidx[j];
                float x = sv[sn] + di;
                x = (x > 0.f) ? x : 0.2f * x;
                w = __expf(x - m);
                Z += w;
            }
            bcast4(sn, w, min(32, end - j0));
        }
        #pragma unroll
        for (int o = 16; o; o >>= 1) Z += __shfl_xor_sync(0xffffffffu, Z, o);
    }

    float invZ = 1.f / (Z + 1e-16f);
    float r0, r1, r2 = 0.f, r3 = 0.f;
    if (V == 4) {
        float4 bb = *reinterpret_cast<const float4*>(bias + 4 * lane);
        r0 = a0 * invZ + bb.x; r1 = a1 * invZ + bb.y;
        r2 = a2 * invZ + bb.z; r3 = a3 * invZ + bb.w;
    } else {
        float2 bb = *reinterpret_cast<const float2*>(bias + 2 * lane);
        r0 = a0 * invZ + bb.x; r1 = a1 * invZ + bb.y;
    }
    if (ACT == 0) {
        r0 = fmaxf(r0, 0.f); r1 = fmaxf(r1, 0.f);
        r2 = fmaxf(r2, 0.f); r3 = fmaxf(r3, 0.f);
    } else {
        r0 = 1.f / (1.f + __expf(-r0)); r1 = 1.f / (1.f + __expf(-r1));
        r2 = 1.f / (1.f + __expf(-r2)); r3 = 1.f / (1.f + __expf(-r3));
    }

    if (OUTH) {
        __half* out = (__half*)outp;
        if (V == 4) {
            uint2 u;
            u.x = h2u(__floats2half2_rn(r0, r1));
            u.y = h2u(__floats2half2_rn(r2, r3));
            *reinterpret_cast<uint2*>(out + (size_t)i * F + 4 * lane) = u;
        } else {
            *reinterpret_cast<__half2*>(out + (size_t)i * F + 2 * lane) =
                __floats2half2_rn(r0, r1);
        }
    } else {
        float* out = (float*)outp;
        if (V == 4)
            *reinterpret_cast<float4*>(out + (size_t)i * F + 4 * lane) =
                make_float4(r0, r1, r2, r3);
        else
            *reinterpret_cast<float2*>(out + (size_t)i * F + 2 * lane) =
                make_float2(r0, r1);
    }
}

// ---------------- host launch ----------------
static inline int cdiv(int a, int b) { return (a + b - 1) / b; }

extern "C" void kernel_launch(void* const* d_in, const int* in_sizes, int n_in,
                              void* d_out, int out_size) {
    const int*   ei    = (const int*)d_in[0];
    const float* embed = (const float*)d_in[1];
    const float* W1    = (const float*)d_in[2];
    const float* as1   = (const float*)d_in[3];
    const float* ad1   = (const float*)d_in[4];
    const float* b1    = (const float*)d_in[5];
    const float* W2    = (const float*)d_in[6];
    const float* as2   = (const float*)d_in[7];
    const float* ad2   = (const float*)d_in[8];
    const float* b2    = (const float*)d_in[9];

    int E = in_sizes[0] / 2;
    int N = in_sizes[1] / CDIM;
    const int* srcv = ei;
    const int* dstv = ei + E;

    void* p;
    cudaGetSymbolAddress(&p, g_deg);    int* deg    = (int*)p;
    cudaGetSymbolAddress(&p, g_incl);   int* incl   = (int*)p;
    cudaGetSymbolAddress(&p, g_bsums);  int* bsums  = (int*)p;
    cudaGetSymbolAddress(&p, g_rowptr); int* rowptr = (int*)p;
    cudaGetSymbolAddress(&p, g_pos);    int* pos    = (int*)p;
    cudaGetSymbolAddress(&p, g_col);    int* col    = (int*)p;
    cudaGetSymbolAddress(&p, g_h1);     __half* h1  = (__half*)p;
    cudaGetSymbolAddress(&p, g_x1);     __half* x1  = (__half*)p;
    cudaGetSymbolAddress(&p, g_h2);     __half* h2  = (__half*)p;
    cudaGetSymbolAddress(&p, g_w1t);    __half* w1t = (__half*)p;
    cudaGetSymbolAddress(&p, g_w2t);    __half* w2t = (__half*)p;
    cudaGetSymbolAddress(&p, g_s1);     float* s1   = (float*)p;
    cudaGetSymbolAddress(&p, g_d1);     float* d1   = (float*)p;
    cudaGetSymbolAddress(&p, g_s2);     float* s2   = (float*)p;
    cudaGetSymbolAddress(&p, g_d2);     float* d2   = (float*)p;
    float* out = (float*)d_out;

    int nb = cdiv(N, 1024);

    constexpr int SMEM1 = (2 * 128 * 40 + 128 * (CDIM + 8)) * 2;  // 88064
    constexpr int SMEM2 = (2 * 128 * 40 + 64 * (HDIM + 8)) * 2;   // 37888

    static cudaStream_t s_side = nullptr;
    static cudaEvent_t ev_fork = nullptr, ev_join = nullptr;
    if (!s_side) {
        cudaStreamCreateWithFlags(&s_side, cudaStreamNonBlocking);
        cudaEventCreateWithFlags(&ev_fork, cudaEventDisableTiming);
        cudaEventCreateWithFlags(&ev_join, cudaEventDisableTiming);
        cudaFuncSetAttribute(mma_gemm_kernel<HDIM, CDIM, true>,
                             cudaFuncAttributeMaxDynamicSharedMemorySize, SMEM1);
        cudaFuncSetAttribute(mma_gemm_kernel<KOUT, HDIM, false>,
                             cudaFuncAttributeMaxDynamicSharedMemorySize, SMEM2);
    }

    // fork: CSR build on side stream (depends only on edge_index)
    cudaEventRecord(ev_fork, 0);
    cudaStreamWaitEvent(s_side, ev_fork, 0);
    cudaMemsetAsync(deg, 0, N * sizeof(int), s_side);
    hist_kernel<<<cdiv(E, 256), 256, 0, s_side>>>(dstv, deg, E);
    scan_block_kernel<<<nb, 1024, 0, s_side>>>(deg, incl, bsums, N);
    scan_bsums_kernel<<<1, 128, 0, s_side>>>(bsums, nb);
    finalize_rowptr_kernel<<<cdiv(N + 1, 256), 256, 0, s_side>>>(incl, bsums, deg, rowptr, pos, N);
    scatter_kernel<<<cdiv(E + N, 256), 256, 0, s_side>>>(srcv, dstv, pos, col, E, N);
    cudaEventRecord(ev_join, s_side);

    // main (overlapped with CSR): weights + GEMM1 (embed loads use L2::evict_first)
    wtrans_both_kernel<<<cdiv(HDIM * CDIM + KOUT * HDIM, 256), 256>>>(W1, w1t, W2, w2t);
    mma_gemm_kernel<HDIM, CDIM, true><<<cdiv(N, 128), 256, SMEM1>>>(
        embed, w1t, h1, as1, ad1, s1, d1, N);

    // join: aggregation needs CSR + h1 (h1 L2-resident thanks to evict-first embed stream)
    cudaStreamWaitEvent(0, ev_join, 0);
    aggregate_kernel<HDIM, 0, true><<<cdiv(N, 8), 256>>>(h1, s1, d1, rowptr, col, b1, x1, N);

    mma_gemm_kernel<KOUT, HDIM, false><<<cdiv(N, 128), 256, SMEM2>>>(
        x1, w2t, h2, as2, ad2, s2, d2, N);
    aggregate_kernel<KOUT, 1, false><<<cdiv(N, 8), 256>>>(h2, s2, d2, rowptr, col, b2, out, N);
}

// round 17
// speedup vs baseline: 1.0425x; 1.0100x over previous
#include <cuda_runtime.h>
#include <cuda_fp16.h>
#include <math.h>
#include <stdint.h>

// Problem-fixed shapes: N=100000, C=256, H=128, K=64, E=1600000
#define NN   100000
#define EE   1600000
#define ETOT (EE + NN)
#define CDIM 256
#define HDIM 128
#define KOUT 64

// ---------------- device scratch (static, no allocation) ----------------
__device__ int    g_deg[NN];
__device__ int    g_incl[NN];
__device__ int    g_bsums[256];
__device__ int    g_rowptr[NN + 1];
__device__ int    g_pos[NN];
__device__ int    g_col[ETOT];
__device__ __half g_h1[NN * HDIM];
__device__ __half g_x1[NN * HDIM];
__device__ __half g_h2[NN * KOUT];
__device__ __half g_w1t[HDIM * CDIM];
__device__ __half g_w2t[KOUT * HDIM];
__device__ float  g_s1[NN], g_d1[NN], g_s2[NN], g_d2[NN];

// ---------------- combined weight transpose + fp16 convert ----------------
__global__ void wtrans_both_kernel(const float* __restrict__ W1, __half* __restrict__ WT1,
                                   const float* __restrict__ W2, __half* __restrict__ WT2) {
    int idx = blockIdx.x * blockDim.x + threadIdx.x;
    if (idx < HDIM * CDIM) {
        int n = idx / CDIM, k = idx % CDIM;
        WT1[idx] = __float2half(W1[(size_t)k * HDIM + n]);
    } else if (idx < HDIM * CDIM + KOUT * HDIM) {
        int j = idx - HDIM * CDIM;
        int n = j / HDIM, k = j % HDIM;
        WT2[j] = __float2half(W2[(size_t)k * KOUT + n]);
    }
}

// ---------------- CSR build (deg = edge count; +1 self-loop folded in finalize) ----------------
__global__ void hist_kernel(const int* __restrict__ dst, int* deg, int e) {
    int i = blockIdx.x * blockDim.x + threadIdx.x;
    if (i < e) atomicAdd(&deg[dst[i]], 1);
}
__global__ void scan_block_kernel(const int* __restrict__ deg, int* incl, int* bsums, int n) {
    __shared__ int sh[1024];
    int t = threadIdx.x;
    int gid = blockIdx.x * 1024 + t;
    sh[t] = (gid < n) ? deg[gid] : 0;
    __syncthreads();
    #pragma unroll
    for (int off = 1; off < 1024; off <<= 1) {
        int v = (t >= off) ? sh[t - off] : 0;
        __syncthreads();
        sh[t] += v;
        __syncthreads();
    }
    if (gid < n) incl[gid] = sh[t];
    if (t == 1023) bsums[blockIdx.x] = sh[t];
}
__global__ void scan_bsums_kernel(int* bsums, int nb) {
    __shared__ int sh[128];
    int t = threadIdx.x;
    sh[t] = (t < nb) ? bsums[t] : 0;
    __syncthreads();
    #pragma unroll
    for (int off = 1; off < 128; off <<= 1) {
        int v = (t >= off) ? sh[t - off] : 0;
        __syncthreads();
        sh[t] += v;
        __syncthreads();
    }
    if (t < nb) bsums[t] = (t == 0) ? 0 : sh[t - 1];
}
__global__ void finalize_rowptr_kernel(const int* __restrict__ incl, const int* __restrict__ bsums,
                                       const int* __restrict__ deg, int* rowptr, int* pos, int n) {
    int gid = blockIdx.x * blockDim.x + threadIdx.x;
    if (gid < n) {
        int v = incl[gid] + bsums[gid >> 10];
        rowptr[gid + 1] = v + gid + 1;
        pos[gid] = v + gid - deg[gid];
    }
    if (gid == 0) rowptr[0] = 0;
}
__global__ void scatter_kernel(const int* __restrict__ srcv, const int* __restrict__ dstv,
                               int* pos, int* colv, int e, int n) {
    int i = blockIdx.x * blockDim.x + threadIdx.x;
    if (i < e) {
        int p = atomicAdd(&pos[dstv[i]], 1);
        colv[p] = srcv[i];
    } else if (i < e + n) {
        int v = i - e;
        int p = atomicAdd(&pos[v], 1);
        colv[p] = v;
    }
}

// ---------------- asm helpers ----------------
__device__ __forceinline__ void cp_async16(void* smem_dst, const void* gmem_src, bool pred) {
    uint32_t saddr = (uint32_t)__cvta_generic_to_shared(smem_dst);
    int sz = pred ? 16 : 0;
    asm volatile("cp.async.cg.shared.global [%0], [%1], 16, %2;\n"
                 :: "r"(saddr), "l"(gmem_src), "r"(sz));
}
__device__ __forceinline__ void cp_commit() {
    asm volatile("cp.async.commit_group;\n");
}
template <int N>
__device__ __forceinline__ void cp_wait() {
    asm volatile("cp.async.wait_group %0;\n" :: "n"(N));
}
__device__ __forceinline__ uint32_t h2u(__half2 h) { return *reinterpret_cast<uint32_t*>(&h); }
__device__ __forceinline__ void ldsm_x4(uint32_t& r0, uint32_t& r1, uint32_t& r2, uint32_t& r3,
                                        uint32_t addr) {
    asm volatile("ldmatrix.sync.aligned.m8n8.x4.shared.b16 {%0,%1,%2,%3}, [%4];"
                 : "=r"(r0), "=r"(r1), "=r"(r2), "=r"(r3) : "r"(addr));
}
// 32B streaming read (v8.b32 is the minimum width ptxas accepts for L2::evict_first)
__device__ __forceinline__ void ldg_stream8(const float* p, float4& lo, float4& hi) {
    asm volatile("ld.global.nc.L2::evict_first.v8.f32 {%0,%1,%2,%3,%4,%5,%6,%7}, [%8];"
                 : "=f"(lo.x), "=f"(lo.y), "=f"(lo.z), "=f"(lo.w),
                   "=f"(hi.x), "=f"(hi.y), "=f"(hi.z), "=f"(hi.w) : "l"(p));
}

// ---------------- fp16 GEMM (m16n8k16): B fully preloaded, A 2-stage ----------------
template <int BN, int KD, bool CONVA>
__global__ __launch_bounds__(256) void mma_gemm_kernel(const void* __restrict__ Ap,
                                                       const __half* __restrict__ BT,
                                                       __half* __restrict__ Cmat,
                                                       const float* __restrict__ asrc,
                                                       const float* __restrict__ adst,
                                                       float* __restrict__ sv,
                                                       float* __restrict__ dv,
                                                       int M, int rowOff) {
    constexpr int BM = 128, BK = 32;
    constexpr int WN = BN / 4;
    constexpr int MT = 4;
    constexpr int NT = WN / 8;
    constexpr int ST  = 40;
    constexpr int ST2 = KD + 8;
    constexpr int T = KD / BK;

    extern __shared__ __half sm[];
    __half* As = sm;                      // [2][BM][ST]
    __half* Bf = sm + 2 * BM * ST;        // [BN][ST2]

    int tid = threadIdx.x;
    int lane = tid & 31;
    int wid = tid >> 5;
    int wm = wid & 1;
    int wn = wid >> 1;
    int rowBase = blockIdx.x * BM + rowOff;

    const float*  Af = (const float*)Ap;
    const __half* Ah = (const __half*)Ap;

    float acc[MT][NT][4];
    #pragma unroll
    for (int i = 0; i < MT; i++)
        #pragma unroll
        for (int j = 0; j < NT; j++)
            #pragma unroll
            for (int r = 0; r < 4; r++) acc[i][j][r] = 0.f;

    {
        constexpr int QR = KD / 8;
        constexpr int CH = BN * QR;
        constexpr int BIT = CH / 256;
        #pragma unroll
        for (int it = 0; it < BIT; it++) {
            int idx = tid + 256 * it;
            int n = idx / QR;
            int q = idx % QR;
            cp_async16(&Bf[n * ST2 + 8 * q], BT + (size_t)n * KD + 8 * q, true);
        }
        cp_commit();
    }

    float4 pa[2][2];
    auto ldgA = [&](int k0) {
        #pragma unroll
        for (int it = 0; it < 2; it++) {
            int idx = tid + 256 * it;
            int row = idx >> 2;
            int q = idx & 3;
            int gr = rowBase + row;
            if (gr < M) {
                ldg_stream8(Af + (size_t)gr * KD + k0 + 8 * q, pa[it][0], pa[it][1]);
            } else {
                pa[it][0] = make_float4(0.f, 0.f, 0.f, 0.f);
                pa[it][1] = make_float4(0.f, 0.f, 0.f, 0.f);
            }
        }
    };
    auto stsA = [&](int stage) {
        #pragma unroll
        for (int it = 0; it < 2; it++) {
            int idx = tid + 256 * it;
            int row = idx >> 2;
            int q = idx & 3;
            uint4 u;
            u.x = h2u(__floats2half2_rn(pa[it][0].x, pa[it][0].y));
            u.y = h2u(__floats2half2_rn(pa[it][0].z, pa[it][0].w));
            u.z = h2u(__floats2half2_rn(pa[it][1].x, pa[it][1].y));
            u.w = h2u(__floats2half2_rn(pa[it][1].z, pa[it][1].w));
            *reinterpret_cast<uint4*>(&As[(stage * BM + row) * ST + 8 * q]) = u;
        }
    };
    auto cpA = [&](int stage, int k0) {
        #pragma unroll
        for (int it = 0; it < 2; it++) {
            int idx = tid + 256 * it;
            int row = idx >> 2;
            int q = idx & 3;
            int gr = rowBase + row;
            cp_async16(&As[(stage * BM + row) * ST + 8 * q],
                       Ah + (size_t)gr * KD + k0 + 8 * q, gr < M);
        }
        cp_commit();
    };

    if (CONVA) ldgA(0);
    else       cpA(0, 0);

    int g = lane >> 3;
    int gl = lane & 7;

    for (int t = 0; t < T; t++) {
        int st = t & 1;
        if (CONVA) {
            stsA(st);
            if (t + 1 < T) ldgA((t + 1) * BK);
            if (t == 0) cp_wait<0>();
        } else {
            if (t + 1 < T) { cpA(st ^ 1, (t + 1) * BK); cp_wait<1>(); }
            else cp_wait<0>();
        }
        __syncthreads();

        #pragma unroll
        for (int kk = 0; kk < 2; kk++) {
            int kglob = t * BK + 16 * kk;
            uint32_t af[MT][4];
            #pragma unroll
            for (int mt = 0; mt < MT; mt++) {
                int row = wm * 64 + mt * 16 + ((g & 1) << 3) + gl;
                int colh = 16 * kk + ((g >> 1) << 3);
                uint32_t addr = (uint32_t)__cvta_generic_to_shared(
                    &As[(st * BM + row) * ST + colh]);
                ldsm_x4(af[mt][0], af[mt][1], af[mt][2], af[mt][3], addr);
            }
            uint32_t bf[NT][2];
            #pragma unroll
            for (int ntp = 0; ntp < NT / 2; ntp++) {
                int n = wn * WN + ntp * 16 + ((g >> 1) << 3) + gl;
                int colh = kglob + ((g & 1) << 3);
                uint32_t addr = (uint32_t)__cvta_generic_to_shared(&Bf[n * ST2 + colh]);
                ldsm_x4(bf[2 * ntp][0], bf[2 * ntp][1], bf[2 * ntp + 1][0], bf[2 * ntp + 1][1], addr);
            }
            #pragma unroll
            for (int mt = 0; mt < MT; mt++)
                #pragma unroll
                for (int nt = 0; nt < NT; nt++) {
                    asm volatile(
                        "mma.sync.aligned.m16n8k16.row.col.f32.f16.f16.f32 "
                        "{%0,%1,%2,%3}, {%4,%5,%6,%7}, {%8,%9}, {%0,%1,%2,%3};"
                        : "+f"(acc[mt][nt][0]), "+f"(acc[mt][nt][1]),
                          "+f"(acc[mt][nt][2]), "+f"(acc[mt][nt][3])
                        : "r"(af[mt][0]), "r"(af[mt][1]), "r"(af[mt][2]), "r"(af[mt][3]),
                          "r"(bf[nt][0]), "r"(bf[nt][1]));
                }
        }
        __syncthreads();
    }

    float* sred = reinterpret_cast<float*>(As);  // [2][BM]
    for (int t = tid; t < 2 * BM; t += 256) sred[t] = 0.f;
    __syncthreads();

    #pragma unroll
    for (int mt = 0; mt < MT; mt++) {
        int rl = wm * 64 + mt * 16 + (lane >> 2);
        int r0 = rowBase + rl;
        float s_lo = 0.f, d_lo = 0.f, s_hi = 0.f, d_hi = 0.f;
        #pragma unroll
        for (int nt = 0; nt < NT; nt++) {
            int col = wn * WN + nt * 8 + 2 * (lane & 3);
            float a0 = asrc[col], a1 = asrc[col + 1];
            float e0 = adst[col], e1 = adst[col + 1];
            s_lo += acc[mt][nt][0] * a0 + acc[mt][nt][1] * a1;
            d_lo += acc[mt][nt][0] * e0 + acc[mt][nt][1] * e1;
            s_hi += acc[mt][nt][2] * a0 + acc[mt][nt][3] * a1;
            d_hi += acc[mt][nt][2] * e0 + acc[mt][nt][3] * e1;
            if (r0 < M)
                *reinterpret_cast<__half2*>(Cmat + (size_t)r0 * BN + col) =
                    __floats2half2_rn(acc[mt][nt][0], acc[mt][nt][1]);
            if (r0 + 8 < M)
                *reinterpret_cast<__half2*>(Cmat + (size_t)(r0 + 8) * BN + col) =
                    __floats2half2_rn(acc[mt][nt][2], acc[mt][nt][3]);
        }
        #pragma unroll
        for (int o = 1; o <= 2; o <<= 1) {
            s_lo += __shfl_xor_sync(0xffffffffu, s_lo, o);
            d_lo += __shfl_xor_sync(0xffffffffu, d_lo, o);
            s_hi += __shfl_xor_sync(0xffffffffu, s_hi, o);
            d_hi += __shfl_xor_sync(0xffffffffu, d_hi, o);
        }
        if ((lane & 3) == 0) {
            atomicAdd(&sred[rl], s_lo);
            atomicAdd(&sred[BM + rl], d_lo);
            atomicAdd(&sred[rl + 8], s_hi);
            atomicAdd(&sred[BM + rl + 8], d_hi);
        }
    }
    __syncthreads();
    for (int t = tid; t < BM; t += 256) {
        int gr = rowBase + t;
        if (gr < M) { sv[gr] = sred[t]; dv[gr] = sred[BM + t]; }
    }
}

// ---------------- aggregation (fp16 gather; proven bcast4 form), node range [n0,n1) ----------------
template <int F, int ACT, bool OUTH>
__global__ __launch_bounds__(256) void aggregate_kernel(
        const __half* __restrict__ h, const float* __restrict__ sv,
        const float* __restrict__ dv, const int* __restrict__ rowptr,
        const int* __restrict__ colidx, const float* __restrict__ bias,
        void* __restrict__ outp, int n0, int n1) {
    constexpr int V = F / 32;
    int warp = n0 + ((blockIdx.x * blockDim.x + threadIdx.x) >> 5);
    int lane = threadIdx.x & 31;
    if (warp >= n1) return;
    int i = warp;
    int start = rowptr[i], end = rowptr[i + 1];
    int len = end - start;
    float di = dv[i];

    float a0 = 0.f, a1 = 0.f, a2 = 0.f, a3 = 0.f;
    float Z = 0.f;

    auto accum = [&](int s, float w) {
        if (V == 4) {
            uint2 u = *reinterpret_cast<const uint2*>(h + (size_t)s * F + 4 * lane);
            float2 f01 = __half22float2(*reinterpret_cast<__half2*>(&u.x));
            float2 f23 = __half22float2(*reinterpret_cast<__half2*>(&u.y));
            a0 += w * f01.x; a1 += w * f01.y; a2 += w * f23.x; a3 += w * f23.y;
        } else {
            __half2 u = *reinterpret_cast<const __half2*>(h + (size_t)s * F + 2 * lane);
            float2 f01 = __half22float2(u);
            a0 += w * f01.x; a1 += w * f01.y;
        }
    };
    auto bcast4 = [&](int sn, float w, int cnt) {
        int tt = 0;
        for (; tt + 4 <= cnt; tt += 4) {
            int s0 = __shfl_sync(0xffffffffu, sn, tt);
            int s1 = __shfl_sync(0xffffffffu, sn, tt + 1);
            int s2 = __shfl_sync(0xffffffffu, sn, tt + 2);
            int s3 = __shfl_sync(0xffffffffu, sn, tt + 3);
            float w0 = __shfl_sync(0xffffffffu, w, tt);
            float w1 = __shfl_sync(0xffffffffu, w, tt + 1);
            float w2 = __shfl_sync(0xffffffffu, w, tt + 2);
            float w3 = __shfl_sync(0xffffffffu, w, tt + 3);
            accum(s0, w0); accum(s1, w1); accum(s2, w2); accum(s3, w3);
        }
        for (; tt < cnt; tt++) {
            int sb = __shfl_sync(0xffffffffu, sn, tt);
            float wb = __shfl_sync(0xffffffffu, w, tt);
            accum(sb, wb);
        }
    };

    if (len <= 32) {
        int sn = 0;
        float x = -INFINITY;
        if (lane < len) {
            sn = colidx[start + lane];
            float xx = sv[sn] + di;
            x = (xx > 0.f) ? xx : 0.2f * xx;
        }
        float m = x;
        #pragma unroll
        for (int o = 16; o; o >>= 1) m = fmaxf(m, __shfl_xor_sync(0xffffffffu, m, o));
        float w = (lane < len) ? __expf(x - m) : 0.f;
        Z = w;
        #pragma unroll
        for (int o = 16; o; o >>= 1) Z += __shfl_xor_sync(0xffffffffu, Z, o);
        bcast4(sn, w, len);
    } else {
        float m = -INFINITY;
        for (int j = start + lane; j < end; j += 32) {
            float x = sv[colidx[j]] + di;
            x = (x > 0.f) ? x : 0.2f * x;
            m = fmaxf(m, x);
        }
        #pragma unroll
        for (int o = 16; o; o >>= 1) m = fmaxf(m, __shfl_xor_sync(0xffffffffu, m, o));

        for (int j0 = start; j0 < end; j0 += 32) {
            int j = j0 + lane;
            int sn = 0;
            float w = 0.f;
            if (j < end) {
                sn = colidx[j];
                float x = sv[sn] + di;
                x = (x > 0.f) ? x : 0.2f * x;
                w = __expf(x - m);
                Z += w;
            }
            bcast4(sn, w, min(32, end - j0));
        }
        #pragma unroll
        for (int o = 16; o; o >>= 1) Z += __shfl_xor_sync(0xffffffffu, Z, o);
    }

    float invZ = 1.f / (Z + 1e-16f);
    float r0, r1, r2 = 0.f, r3 = 0.f;
    if (V == 4) {
        float4 bb = *reinterpret_cast<const float4*>(bias + 4 * lane);
        r0 = a0 * invZ + bb.x; r1 = a1 * invZ + bb.y;
        r2 = a2 * invZ + bb.z; r3 = a3 * invZ + bb.w;
    } else {
        float2 bb = *reinterpret_cast<const float2*>(bias + 2 * lane);
        r0 = a0 * invZ + bb.x; r1 = a1 * invZ + bb.y;
    }
    if (ACT == 0) {
        r0 = fmaxf(r0, 0.f); r1 = fmaxf(r1, 0.f);
        r2 = fmaxf(r2, 0.f); r3 = fmaxf(r3, 0.f);
    } else {
        r0 = 1.f / (1.f + __expf(-r0)); r1 = 1.f / (1.f + __expf(-r1));
        r2 = 1.f / (1.f + __expf(-r2)); r3 = 1.f / (1.f + __expf(-r3));
    }

    if (OUTH) {
        __half* out = (__half*)outp;
        if (V == 4) {
            uint2 u;
            u.x = h2u(__floats2half2_rn(r0, r1));
            u.y = h2u(__floats2half2_rn(r2, r3));
            *reinterpret_cast<uint2*>(out + (size_t)i * F + 4 * lane) = u;
        } else {
            *reinterpret_cast<__half2*>(out + (size_t)i * F + 2 * lane) =
                __floats2half2_rn(r0, r1);
        }
    } else {
        float* out = (float*)outp;
        if (V == 4)
            *reinterpret_cast<float4*>(out + (size_t)i * F + 4 * lane) =
                make_float4(r0, r1, r2, r3);
        else
            *reinterpret_cast<float2*>(out + (size_t)i * F + 2 * lane) =
                make_float2(r0, r1);
    }
}

// ---------------- host launch ----------------
static inline int cdiv(int a, int b) { return (a + b - 1) / b; }

extern "C" void kernel_launch(void* const* d_in, const int* in_sizes, int n_in,
                              void* d_out, int out_size) {
    const int*   ei    = (const int*)d_in[0];
    const float* embed = (const float*)d_in[1];
    const float* W1    = (const float*)d_in[2];
    const float* as1   = (const float*)d_in[3];
    const float* ad1   = (const float*)d_in[4];
    const float* b1    = (const float*)d_in[5];
    const float* W2    = (const float*)d_in[6];
    const float* as2   = (const float*)d_in[7];
    const float* ad2   = (const float*)d_in[8];
    const float* b2    = (const float*)d_in[9];

    int E = in_sizes[0] / 2;
    int N = in_sizes[1] / CDIM;
    const int* srcv = ei;
    const int* dstv = ei + E;

    void* p;
    cudaGetSymbolAddress(&p, g_deg);    int* deg    = (int*)p;
    cudaGetSymbolAddress(&p, g_incl);   int* incl   = (int*)p;
    cudaGetSymbolAddress(&p, g_bsums);  int* bsums  = (int*)p;
    cudaGetSymbolAddress(&p, g_rowptr); int* rowptr = (int*)p;
    cudaGetSymbolAddress(&p, g_pos);    int* pos    = (int*)p;
    cudaGetSymbolAddress(&p, g_col);    int* col    = (int*)p;
    cudaGetSymbolAddress(&p, g_h1);     __half* h1  = (__half*)p;
    cudaGetSymbolAddress(&p, g_x1);     __half* x1  = (__half*)p;
    cudaGetSymbolAddress(&p, g_h2);     __half* h2  = (__half*)p;
    cudaGetSymbolAddress(&p, g_w1t);    __half* w1t = (__half*)p;
    cudaGetSymbolAddress(&p, g_w2t);    __half* w2t = (__half*)p;
    cudaGetSymbolAddress(&p, g_s1);     float* s1   = (float*)p;
    cudaGetSymbolAddress(&p, g_d1);     float* d1   = (float*)p;
    cudaGetSymbolAddress(&p, g_s2);     float* s2   = (float*)p;
    cudaGetSymbolAddress(&p, g_d2);     float* d2   = (float*)p;
    float* out = (float*)d_out;

    int nb = cdiv(N, 1024);

    constexpr int SMEM1 = (2 * 128 * 40 + 128 * (CDIM + 8)) * 2;  // 88064
    constexpr int SMEM2 = (2 * 128 * 40 + 64 * (HDIM + 8)) * 2;   // 37888

    static cudaStream_t s_side = nullptr;
    static cudaEvent_t ev_fork = nullptr, ev_join = nullptr, ev_a1lo = nullptr, ev_g2lo = nullptr;
    if (!s_side) {
        cudaStreamCreateWithFlags(&s_side, cudaStreamNonBlocking);
        cudaEventCreateWithFlags(&ev_fork, cudaEventDisableTiming);
        cudaEventCreateWithFlags(&ev_join, cudaEventDisableTiming);
        cudaEventCreateWithFlags(&ev_a1lo, cudaEventDisableTiming);
        cudaEventCreateWithFlags(&ev_g2lo, cudaEventDisableTiming);
        cudaFuncSetAttribute(mma_gemm_kernel<HDIM, CDIM, true>,
                             cudaFuncAttributeMaxDynamicSharedMemorySize, SMEM1);
        cudaFuncSetAttribute(mma_gemm_kernel<KOUT, HDIM, false>,
                             cudaFuncAttributeMaxDynamicSharedMemorySize, SMEM2);
    }

    const int CH0 = 50048;     // 391 * 128 — chunk boundary for agg1 / GEMM2 pipeline
    const int CH1 = N - CH0;

    // fork: CSR build on side stream (depends only on edge_index)
    cudaEventRecord(ev_fork, 0);
    cudaStreamWaitEvent(s_side, ev_fork, 0);
    cudaMemsetAsync(deg, 0, N * sizeof(int), s_side);
    hist_kernel<<<cdiv(E, 256), 256, 0, s_side>>>(dstv, deg, E);
    scan_block_kernel<<<nb, 1024, 0, s_side>>>(deg, incl, bsums, N);
    scan_bsums_kernel<<<1, 128, 0, s_side>>>(bsums, nb);
    finalize_rowptr_kernel<<<cdiv(N + 1, 256), 256, 0, s_side>>>(incl, bsums, deg, rowptr, pos, N);
    scatter_kernel<<<cdiv(E + N, 256), 256, 0, s_side>>>(srcv, dstv, pos, col, E, N);
    cudaEventRecord(ev_join, s_side);

    // main (overlapped with CSR): weights + GEMM1 (embed loads use L2::evict_first)
    wtrans_both_kernel<<<cdiv(HDIM * CDIM + KOUT * HDIM, 256), 256>>>(W1, w1t, W2, w2t);
    mma_gemm_kernel<HDIM, CDIM, true><<<cdiv(N, 128), 256, SMEM1>>>(
        embed, w1t, h1, as1, ad1, s1, d1, N, 0);

    // join CSR, then agg1 chunk 0
    cudaStreamWaitEvent(0, ev_join, 0);
    aggregate_kernel<HDIM, 0, true><<<cdiv(CH0, 8), 256>>>(
        h1, s1, d1, rowptr, col, b1, x1, 0, CH0);
    cudaEventRecord(ev_a1lo, 0);

    // side: GEMM2 chunk 0 (needs x1[0..CH0) + w2t, both ordered via ev_a1lo)
    cudaStreamWaitEvent(s_side, ev_a1lo, 0);
    mma_gemm_kernel<KOUT, HDIM, false><<<CH0 / 128, 256, SMEM2, s_side>>>(
        x1, w2t, h2, as2, ad2, s2, d2, N, 0);
    cudaEventRecord(ev_g2lo, s_side);

    // main (concurrent with GEMM2_lo): agg1 chunk 1, then GEMM2 chunk 1
    aggregate_kernel<HDIM, 0, true><<<cdiv(CH1, 8), 256>>>(
        h1, s1, d1, rowptr, col, b1, x1, CH0, N);
    mma_gemm_kernel<KOUT, HDIM, false><<<cdiv(CH1, 128), 256, SMEM2>>>(
        x1, w2t, h2, as2, ad2, s2, d2, N, CH0);

    // agg2 needs both GEMM2 chunks
    cudaStreamWaitEvent(0, ev_g2lo, 0);
    aggregate_kernel<KOUT, 1, false><<<cdiv(N, 8), 256>>>(
        h2, s2, d2, rowptr, col, b2, out, 0, N);
}